// round 1
// baseline (speedup 1.0000x reference)
#include <cuda_runtime.h>
#include <math.h>

#define Bsz 2048
#define Nn  20
#define Dd  512
#define Hh  8
#define DKc 64
#define DQc 64
#define KSc 3
#define M_TOT (Bsz*Nn)   // 40960
#define KC (3*Dd)        // 1536
#define NC (3*Dd)        // 1536

// -------- scratch (device globals; no allocation allowed) --------
__device__ float g_wpack[KC * NC];        // packed conv weights [k=(s,i), j=(proj,o)]
__device__ float g_qkv[(size_t)M_TOT * NC]; // conv out, then (after LN) q|k|v
__device__ float g_qf[(size_t)M_TOT * DQc];
__device__ float g_att[(size_t)M_TOT * Dd];

// -------- pack conv weights into GEMM-B layout --------
__global__ void pack_w(const float* __restrict__ Wq, const float* __restrict__ Wk,
                       const float* __restrict__ Wv) {
    int idx = blockIdx.x * blockDim.x + threadIdx.x;
    if (idx >= KC * NC) return;
    int k = idx / NC, j = idx - (idx / NC) * NC;
    int s = k / Dd, i = k - s * Dd;
    int p = j / Dd, o = j - p * Dd;
    const float* W = (p == 0) ? Wq : (p == 1 ? Wk : Wv);
    g_wpack[idx] = W[(o * Dd + i) * KSc + s];   // W[o, i, s]
}

// -------- conv-as-GEMM: [40960,1536] x [1536,1536] -> g_qkv --------
// A[m, k=(s,i)] = x[b, n+s-1, i] (0 outside sequence), built in the tile loader.
__global__ __launch_bounds__(256) void conv_gemm(const float* __restrict__ x) {
    __shared__ float As[16][128];
    __shared__ float Bs[16][128];
    int bm = blockIdx.y * 128, bn = blockIdx.x * 128;
    int tid = threadIdx.x;
    int tr = tid >> 4, tc = tid & 15;
    float acc[8][8] = {};
    for (int k0 = 0; k0 < KC; k0 += 16) {
        #pragma unroll
        for (int i = tid; i < 128 * 16; i += 256) {
            int row = i >> 4, kk = i & 15;
            int m = bm + row, k = k0 + kk;
            int s = k >> 9, ci = k & 511;
            int b = m / Nn;
            int n = m - b * Nn;
            int sn = n + s - 1;
            As[kk][row] = (sn >= 0 && sn < Nn) ? x[(size_t)(b * Nn + sn) * Dd + ci] : 0.f;
        }
        #pragma unroll
        for (int i = tid; i < 16 * 128; i += 256) {
            int kk = i >> 7, col = i & 127;
            Bs[kk][col] = g_wpack[(size_t)(k0 + kk) * NC + bn + col];
        }
        __syncthreads();
        #pragma unroll
        for (int kk = 0; kk < 16; kk++) {
            float a[8], bf[8];
            #pragma unroll
            for (int i = 0; i < 8; i++) a[i] = As[kk][tr * 8 + i];
            #pragma unroll
            for (int j = 0; j < 8; j++) bf[j] = Bs[kk][tc * 8 + j];
            #pragma unroll
            for (int i = 0; i < 8; i++)
                #pragma unroll
                for (int j = 0; j < 8; j++) acc[i][j] += a[i] * bf[j];
        }
        __syncthreads();
    }
    #pragma unroll
    for (int i = 0; i < 8; i++) {
        int m = bm + tr * 8 + i;
        #pragma unroll
        for (int j = 0; j < 8; j++)
            g_qkv[(size_t)m * NC + bn + tc * 8 + j] = acc[i][j];
    }
}

// -------- LayerNorm + residual, in place on g_qkv --------
__global__ void ln_res(const float* __restrict__ x,
                       const float* g0, const float* b0,
                       const float* g1, const float* b1,
                       const float* g2, const float* b2) {
    int m = blockIdx.x, p = blockIdx.y;
    const float* g  = (p == 0) ? g0 : (p == 1 ? g1 : g2);
    const float* bb = (p == 0) ? b0 : (p == 1 ? b1 : b2);
    float* row = g_qkv + (size_t)m * NC + p * Dd;
    int tid = threadIdx.x;          // 128 threads
    float v[4], s = 0.f, s2 = 0.f;
    #pragma unroll
    for (int i = 0; i < 4; i++) {
        v[i] = row[i * 128 + tid];
        s += v[i]; s2 += v[i] * v[i];
    }
    #pragma unroll
    for (int o = 16; o; o >>= 1) {
        s  += __shfl_xor_sync(0xffffffffu, s, o);
        s2 += __shfl_xor_sync(0xffffffffu, s2, o);
    }
    __shared__ float ss[4], ss2[4];
    int w = tid >> 5, l = tid & 31;
    if (l == 0) { ss[w] = s; ss2[w] = s2; }
    __syncthreads();
    if (tid == 0) {
        float t = ss[0] + ss[1] + ss[2] + ss[3];
        float t2 = ss2[0] + ss2[1] + ss2[2] + ss2[3];
        float mean = t * (1.f / 512.f);
        float var = t2 * (1.f / 512.f) - mean * mean;
        ss[0] = mean; ss2[0] = rsqrtf(var + 1e-5f);
    }
    __syncthreads();
    float mean = ss[0], inv = ss2[0];
    #pragma unroll
    for (int i = 0; i < 4; i++) {
        int c = i * 128 + tid;
        row[c] = x[(size_t)m * Dd + c] + (v[i] - mean) * inv * g[c] + bb[c];
    }
}

// -------- qf = tanh(x @ Wqf + bqf) --------
__global__ __launch_bounds__(256) void qf_kernel(const float* __restrict__ x,
                                                 const float* __restrict__ Wqf,
                                                 const float* __restrict__ bqf) {
    __shared__ float xs[4][512];
    int m0 = blockIdx.x * 4;
    int tid = threadIdx.x;
    for (int i = tid; i < 4 * 512; i += 256)
        xs[i >> 9][i & 511] = x[(size_t)(m0 + (i >> 9)) * Dd + (i & 511)];
    __syncthreads();
    int lr = tid >> 6, j = tid & 63;
    float acc = bqf[j];
    #pragma unroll 4
    for (int k = 0; k < 512; k++) acc += xs[lr][k] * Wqf[k * 64 + j];
    g_qf[(size_t)(m0 + lr) * DQc + j] = tanhf(acc);
}

// -------- fused attention per (b, h) --------
__global__ __launch_bounds__(256) void attn_kernel(const float* __restrict__ rel,
                                                   const float* __restrict__ gsb,
                                                   const float* __restrict__ alpha_p,
                                                   const float* __restrict__ Wqp,
                                                   const float* __restrict__ bqp) {
    int bh = blockIdx.x;
    int b = bh >> 3, h = bh & 7;
    int m0 = b * Nn;
    __shared__ float qs[20 * 64], ks_[20 * 64], vs[20 * 64], qfs[20 * 64];
    __shared__ float sc[20][20];
    __shared__ float av[20];
    int tid = threadIdx.x;
    for (int i = tid; i < 1280; i += 256) {
        int n = i >> 6, d = i & 63;
        size_t base = (size_t)(m0 + n) * NC + h * 64 + d;
        qs[i]  = g_qkv[base];
        ks_[i] = g_qkv[base + 512];
        vs[i]  = g_qkv[base + 1024];
        qfs[i] = g_qf[(size_t)(m0 + n) * DQc + d];
    }
    __syncthreads();
    if (tid < 20) {
        float a = 0.f;
        #pragma unroll 8
        for (int j = 0; j < 64; j++) a += qfs[tid * 64 + j] * Wqp[j * 8 + h];
        av[tid] = a;
    }
    __syncthreads();
    float alpha = *alpha_p, bq = bqp[h];
    for (int t = tid; t < 400; t += 256) {
        int nq = t / 20, nk = t - nq * 20;
        float d = 0.f;
        #pragma unroll 8
        for (int j = 0; j < 64; j++) d += qs[nq * 64 + j] * ks_[nk * 64 + j];
        sc[nq][nk] = d * 0.125f
                   + rel[(nq - nk + 19) * 8 + h]
                   + alpha * gsb[h * 400 + nq * 20 + nk]
                   + (av[nq] - av[nk] + bq);
    }
    __syncthreads();
    if (tid < 20) {
        float mx = -1e30f;
        #pragma unroll
        for (int k = 0; k < 20; k++) mx = fmaxf(mx, sc[tid][k]);
        float s = 0.f;
        #pragma unroll
        for (int k = 0; k < 20; k++) { float e = expf(sc[tid][k] - mx); sc[tid][k] = e; s += e; }
        float inv = 1.f / s;
        #pragma unroll
        for (int k = 0; k < 20; k++) sc[tid][k] *= inv;
    }
    __syncthreads();
    for (int i = tid; i < 1280; i += 256) {
        int nq = i >> 6, d = i & 63;
        float o = 0.f;
        #pragma unroll
        for (int nk = 0; nk < 20; nk++) o += sc[nq][nk] * vs[nk * 64 + d];
        g_att[(size_t)(m0 + nq) * Dd + h * 64 + d] = o;
    }
}

// -------- final projection: out = g_att @ Wo + bo --------
__global__ __launch_bounds__(256) void out_gemm(const float* __restrict__ Wo,
                                                const float* __restrict__ bo,
                                                float* __restrict__ out) {
    __shared__ float As[16][128];
    __shared__ float Bs[16][128];
    int bm = blockIdx.y * 128, bn = blockIdx.x * 128;
    int tid = threadIdx.x;
    int tr = tid >> 4, tc = tid & 15;
    float acc[8][8] = {};
    for (int k0 = 0; k0 < 512; k0 += 16) {
        #pragma unroll
        for (int i = tid; i < 128 * 16; i += 256) {
            int row = i >> 4, kk = i & 15;
            As[kk][row] = g_att[(size_t)(bm + row) * Dd + k0 + kk];
        }
        #pragma unroll
        for (int i = tid; i < 16 * 128; i += 256) {
            int kk = i >> 7, col = i & 127;
            Bs[kk][col] = Wo[(size_t)(k0 + kk) * Dd + bn + col];
        }
        __syncthreads();
        #pragma unroll
        for (int kk = 0; kk < 16; kk++) {
            float a[8], bf[8];
            #pragma unroll
            for (int i = 0; i < 8; i++) a[i] = As[kk][tr * 8 + i];
            #pragma unroll
            for (int j = 0; j < 8; j++) bf[j] = Bs[kk][tc * 8 + j];
            #pragma unroll
            for (int i = 0; i < 8; i++)
                #pragma unroll
                for (int j = 0; j < 8; j++) acc[i][j] += a[i] * bf[j];
        }
        __syncthreads();
    }
    #pragma unroll
    for (int i = 0; i < 8; i++) {
        int m = bm + tr * 8 + i;
        #pragma unroll
        for (int j = 0; j < 8; j++) {
            int c = bn + tc * 8 + j;
            out[(size_t)m * Dd + c] = acc[i][j] + bo[c];
        }
    }
}

extern "C" void kernel_launch(void* const* d_in, const int* in_sizes, int n_in,
                              void* d_out, int out_size) {
    const float* x   = (const float*)d_in[0];
    const float* Wq  = (const float*)d_in[1];
    const float* Wk  = (const float*)d_in[2];
    const float* Wv  = (const float*)d_in[3];
    const float* gqg = (const float*)d_in[4];
    const float* gqb = (const float*)d_in[5];
    const float* gkg = (const float*)d_in[6];
    const float* gkb = (const float*)d_in[7];
    const float* gvg = (const float*)d_in[8];
    const float* gvb = (const float*)d_in[9];
    const float* rel = (const float*)d_in[10];
    const float* gsb = (const float*)d_in[11];
    const float* alp = (const float*)d_in[12];
    const float* Wqf = (const float*)d_in[13];
    const float* bqf = (const float*)d_in[14];
    const float* Wqp = (const float*)d_in[15];
    const float* bqp = (const float*)d_in[16];
    const float* Wo  = (const float*)d_in[17];
    const float* bo  = (const float*)d_in[18];
    float* out = (float*)d_out;

    pack_w<<<(KC * NC + 255) / 256, 256>>>(Wq, Wk, Wv);

    dim3 g1(NC / 128, M_TOT / 128);          // 12 x 320
    conv_gemm<<<g1, 256>>>(x);

    dim3 g2(M_TOT, 3);
    ln_res<<<g2, 128>>>(x, gqg, gqb, gkg, gkb, gvg, gvb);

    qf_kernel<<<M_TOT / 4, 256>>>(x, Wqf, bqf);

    attn_kernel<<<Bsz * Hh, 256>>>(rel, gsb, alp, Wqp, bqp);

    dim3 g3(Dd / 128, M_TOT / 128);          // 4 x 320
    out_gemm<<<g3, 256>>>(Wo, bo, out);
}

// round 3
// speedup vs baseline: 2.4854x; 2.4854x over previous
#include <cuda_runtime.h>
#include <cuda_bf16.h>
#include <math.h>
#include <stdint.h>

#define Bsz 2048
#define Nn  20
#define Dd  512
#define Hh  8
#define M_TOT (Bsz*Nn)   // 40960
#define KC 1536          // conv GEMM K
#define NC 1536          // q|k|v cols
#define NCP 1664         // padded B rows (1536 qkv + 64 qf + 64 zero) = 13*128

// ---------------- device scratch ----------------
__device__ __nv_bfloat16 g_x_hi[(size_t)M_TOT * Dd];
__device__ __nv_bfloat16 g_x_lo[(size_t)M_TOT * Dd];
__device__ __nv_bfloat16 g_wpt_hi[(size_t)NCP * KC];   // B^T for conv (+qf cols)
__device__ __nv_bfloat16 g_wpt_lo[(size_t)NCP * KC];
__device__ __nv_bfloat16 g_wot_hi[(size_t)Dd * Dd];    // Wo^T
__device__ __nv_bfloat16 g_wot_lo[(size_t)Dd * Dd];
__device__ float g_qkv[(size_t)M_TOT * NC];
__device__ float g_qf[(size_t)M_TOT * 64];
__device__ __nv_bfloat16 g_att_hi[(size_t)M_TOT * Dd];
__device__ __nv_bfloat16 g_att_lo[(size_t)M_TOT * Dd];

// ---------------- helpers ----------------
__device__ __forceinline__ uint32_t smem_u32(const void* p) {
    uint32_t a;
    asm("{ .reg .u64 t; cvta.to.shared.u64 t, %1; cvt.u32.u64 %0, t; }" : "=r"(a) : "l"(p));
    return a;
}
#define LDSM4(r, addr) \
    asm volatile("ldmatrix.sync.aligned.m8n8.x4.shared.b16 {%0,%1,%2,%3}, [%4];" \
        : "=r"((r)[0]), "=r"((r)[1]), "=r"((r)[2]), "=r"((r)[3]) : "r"(addr))

__device__ __forceinline__ void mma16816(float* d, const uint32_t* a, const uint32_t* b) {
    asm volatile(
        "mma.sync.aligned.m16n8k16.row.col.f32.bf16.bf16.f32 "
        "{%0,%1,%2,%3}, {%4,%5,%6,%7}, {%8,%9}, {%0,%1,%2,%3};"
        : "+f"(d[0]), "+f"(d[1]), "+f"(d[2]), "+f"(d[3])
        : "r"(a[0]), "r"(a[1]), "r"(a[2]), "r"(a[3]), "r"(b[0]), "r"(b[1]));
}
__device__ __forceinline__ void cp16(uint32_t dst, const void* src, uint32_t sz) {
    asm volatile("cp.async.cg.shared.global [%0], [%1], 16, %2;" :: "r"(dst), "l"(src), "r"(sz) : "memory");
}
#define CP_COMMIT() asm volatile("cp.async.commit_group;" ::: "memory")
#define CP_WAIT1()  asm volatile("cp.async.wait_group 1;" ::: "memory")
#define CP_WAIT0()  asm volatile("cp.async.wait_group 0;" ::: "memory")

// ---------------- conversions / packing ----------------
__global__ void x2hl(const float* __restrict__ x) {
    size_t i = (size_t)(blockIdx.x * blockDim.x + threadIdx.x) * 4;
    #pragma unroll
    for (int u = 0; u < 4; u++) {
        float v = x[i + u];
        __nv_bfloat16 hi = __float2bfloat16(v);
        g_x_hi[i + u] = hi;
        g_x_lo[i + u] = __float2bfloat16(v - __bfloat162float(hi));
    }
}

__global__ void pack_w_t(const float* __restrict__ Wq, const float* __restrict__ Wk,
                         const float* __restrict__ Wv, const float* __restrict__ Wqf) {
    int idx = blockIdx.x * blockDim.x + threadIdx.x;   // over NCP*KC
    if (idx >= NCP * KC) return;
    int j = idx / KC, k = idx - (idx / KC) * KC;
    float w = 0.f;
    if (j < NC) {
        int p = j >> 9, o = j & 511;
        int s = k >> 9, i = k & 511;
        const float* W = (p == 0) ? Wq : (p == 1 ? Wk : Wv);
        w = W[(o * Dd + i) * 3 + s];
    } else if (j < NC + 64) {
        int jj = j - NC;
        if ((k >> 9) == 1) w = Wqf[(k & 511) * 64 + jj];
    }
    __nv_bfloat16 hi = __float2bfloat16(w);
    g_wpt_hi[(size_t)j * KC + k] = hi;
    g_wpt_lo[(size_t)j * KC + k] = __float2bfloat16(w - __bfloat162float(hi));
}

__global__ void pack_wo_t(const float* __restrict__ Wo) {
    int idx = blockIdx.x * blockDim.x + threadIdx.x;   // over 512*512
    int j = idx >> 9, k = idx & 511;
    float w = Wo[(size_t)k * Dd + j];
    __nv_bfloat16 hi = __float2bfloat16(w);
    g_wot_hi[(size_t)j * Dd + k] = hi;
    g_wot_lo[(size_t)j * Dd + k] = __float2bfloat16(w - __bfloat162float(hi));
}

// ---------------- mma.sync GEMM: 128x128 tiles, K=32 double-buffered ----------------
// smem stage: 4 matrices (Ah, Al, Bh, Bl), each 128 rows x 40 bf16 (32 used, 8 pad)
#define ROWP 40
#define MATB (128 * ROWP * 2)          // 10240 B
#define STAGE_B (4 * MATB)             // 40960 B
#define GSMEM (2 * STAGE_B)            // 81920 B

template<int KDIM, bool CONV>
__global__ __launch_bounds__(256) void mma_gemm(float* __restrict__ Cout,
                                                const float* __restrict__ bias,
                                                const float* __restrict__ bqf) {
    extern __shared__ char smc[];
    const uint32_t sbase = smem_u32(smc);
    const int tid = threadIdx.x;
    const int bm = blockIdx.y * 128, bn = blockIdx.x * 128;
    const int NCH = KDIM / 32;

    const __nv_bfloat16* Ahi = CONV ? g_x_hi : g_att_hi;
    const __nv_bfloat16* Alo = CONV ? g_x_lo : g_att_lo;
    const __nv_bfloat16* Bhi = CONV ? g_wpt_hi : g_wot_hi;
    const __nv_bfloat16* Blo = CONV ? g_wpt_lo : g_wot_lo;

    auto load_stage = [&](int c) {
        const int k0 = c * 32;
        const uint32_t sb = sbase + (c & 1) * STAGE_B;
        #pragma unroll
        for (int i = 0; i < 8; i++) {
            int t = tid + i * 256;
            int mat = t >> 9, idx = t & 511, row = idx >> 2, q = idx & 3;
            uint32_t dst = sb + mat * MATB + (row * ROWP + q * 8) * 2;
            const __nv_bfloat16* src;
            uint32_t sz = 16;
            if (mat < 2) {
                const __nv_bfloat16* base = mat ? Alo : Ahi;
                if (CONV) {
                    int m = bm + row;
                    int b = m / Nn, n = m - b * Nn;
                    int sn = n + (k0 >> 9) - 1;
                    int snc = sn < 0 ? 0 : (sn >= Nn ? Nn - 1 : sn);
                    if (sn != snc) sz = 0;
                    src = base + (((size_t)(b * Nn + snc)) << 9) + (k0 & 511) + q * 8;
                } else {
                    src = base + (size_t)(bm + row) * KDIM + k0 + q * 8;
                }
            } else {
                const __nv_bfloat16* base = (mat == 2) ? Bhi : Blo;
                src = base + (size_t)(bn + row) * KDIM + k0 + q * 8;
            }
            cp16(dst, src, sz);
        }
        CP_COMMIT();
    };

    const int lane = tid & 31, wid = tid >> 5;
    const int wm = (wid >> 2) * 64, wn = (wid & 3) * 32;
    float acc[4][4][4];
    #pragma unroll
    for (int a = 0; a < 4; a++)
        #pragma unroll
        for (int b = 0; b < 4; b++)
            #pragma unroll
            for (int d = 0; d < 4; d++) acc[a][b][d] = 0.f;

    load_stage(0);

    for (int c = 0; c < NCH; c++) {
        if (c + 1 < NCH) { load_stage(c + 1); CP_WAIT1(); }
        else             { CP_WAIT0(); }
        __syncthreads();
        const uint32_t sb = sbase + (c & 1) * STAGE_B;
        #pragma unroll
        for (int kk = 0; kk < 2; kk++) {
            const int koff = kk * 16 + ((lane >> 4) << 3);
            const int arow = lane & 15;
            uint32_t a_h[4][4], a_l[4][4], b_h[4][2], b_l[4][2];
            #pragma unroll
            for (int mt = 0; mt < 4; mt++) {
                uint32_t ad = sb + ((wm + mt * 16 + arow) * ROWP + koff) * 2;
                LDSM4(a_h[mt], ad);
                LDSM4(a_l[mt], ad + MATB);
            }
            const int brow = ((lane >> 4) << 3) + (lane & 7);
            const int bkoff = kk * 16 + (((lane >> 3) & 1) << 3);
            #pragma unroll
            for (int pr = 0; pr < 2; pr++) {
                uint32_t bd = sb + 2 * MATB + ((wn + pr * 16 + brow) * ROWP + bkoff) * 2;
                uint32_t r[4];
                LDSM4(r, bd);
                b_h[pr * 2][0] = r[0]; b_h[pr * 2][1] = r[1];
                b_h[pr * 2 + 1][0] = r[2]; b_h[pr * 2 + 1][1] = r[3];
                LDSM4(r, bd + MATB);
                b_l[pr * 2][0] = r[0]; b_l[pr * 2][1] = r[1];
                b_l[pr * 2 + 1][0] = r[2]; b_l[pr * 2 + 1][1] = r[3];
            }
            #pragma unroll
            for (int mt = 0; mt < 4; mt++)
                #pragma unroll
                for (int nt = 0; nt < 4; nt++) {
                    mma16816(acc[mt][nt], a_h[mt], b_h[nt]);
                    mma16816(acc[mt][nt], a_h[mt], b_l[nt]);
                    mma16816(acc[mt][nt], a_l[mt], b_h[nt]);
                }
        }
        __syncthreads();
    }

    // ---------------- epilogue ----------------
    const int g = lane >> 2, tg = lane & 3;
    #pragma unroll
    for (int mt = 0; mt < 4; mt++) {
        #pragma unroll
        for (int nt = 0; nt < 4; nt++) {
            int j = bn + wn + nt * 8 + tg * 2;
            #pragma unroll
            for (int half = 0; half < 2; half++) {
                int m = bm + wm + mt * 16 + g + half * 8;
                float d0 = acc[mt][nt][half * 2], d1 = acc[mt][nt][half * 2 + 1];
                if (CONV) {
                    if (j < NC) {
                        float2 v = make_float2(d0, d1);
                        *(float2*)(g_qkv + (size_t)m * NC + j) = v;
                    } else if (j < NC + 64) {
                        int jj = j - NC;
                        float2 v = make_float2(tanhf(d0 + bqf[jj]), tanhf(d1 + bqf[jj + 1]));
                        *(float2*)(g_qf + (size_t)m * 64 + jj) = v;
                    }
                } else {
                    float2 v = make_float2(d0 + bias[j], d1 + bias[j + 1]);
                    *(float2*)(Cout + (size_t)m * KDIM + j) = v;
                }
            }
        }
    }
}

// ---------------- LayerNorm + residual (in place on g_qkv) ----------------
__global__ void ln_res(const float* __restrict__ x,
                       const float* g0, const float* b0,
                       const float* g1, const float* b1,
                       const float* g2, const float* b2) {
    int m = blockIdx.x, p = blockIdx.y;
    const float* g  = (p == 0) ? g0 : (p == 1 ? g1 : g2);
    const float* bb = (p == 0) ? b0 : (p == 1 ? b1 : b2);
    float* row = g_qkv + (size_t)m * NC + p * Dd;
    int tid = threadIdx.x;
    float v[4], s = 0.f, s2 = 0.f;
    #pragma unroll
    for (int i = 0; i < 4; i++) {
        v[i] = row[i * 128 + tid];
        s += v[i]; s2 += v[i] * v[i];
    }
    #pragma unroll
    for (int o = 16; o; o >>= 1) {
        s  += __shfl_xor_sync(0xffffffffu, s, o);
        s2 += __shfl_xor_sync(0xffffffffu, s2, o);
    }
    __shared__ float ss[4], ss2[4];
    int w = tid >> 5, l = tid & 31;
    if (l == 0) { ss[w] = s; ss2[w] = s2; }
    __syncthreads();
    if (tid == 0) {
        float t = ss[0] + ss[1] + ss[2] + ss[3];
        float t2 = ss2[0] + ss2[1] + ss2[2] + ss2[3];
        float mean = t * (1.f / 512.f);
        float var = t2 * (1.f / 512.f) - mean * mean;
        ss[0] = mean; ss2[0] = rsqrtf(var + 1e-5f);
    }
    __syncthreads();
    float mean = ss[0], inv = ss2[0];
    #pragma unroll
    for (int i = 0; i < 4; i++) {
        int c = i * 128 + tid;
        row[c] = x[(size_t)m * Dd + c] + (v[i] - mean) * inv * g[c] + bb[c];
    }
}

// ---------------- fused attention per (b, h); writes hi/lo bf16 ----------------
__global__ __launch_bounds__(256) void attn_kernel(const float* __restrict__ rel,
                                                   const float* __restrict__ gsb,
                                                   const float* __restrict__ alpha_p,
                                                   const float* __restrict__ Wqp,
                                                   const float* __restrict__ bqp) {
    int bh = blockIdx.x;
    int b = bh >> 3, h = bh & 7;
    int m0 = b * Nn;
    __shared__ float qs[20 * 64], ks_[20 * 64], vs[20 * 64], qfs[20 * 64];
    __shared__ float sc[20][20];
    __shared__ float av[20];
    int tid = threadIdx.x;
    for (int i = tid; i < 1280; i += 256) {
        int n = i >> 6, d = i & 63;
        size_t base = (size_t)(m0 + n) * NC + h * 64 + d;
        qs[i]  = g_qkv[base];
        ks_[i] = g_qkv[base + 512];
        vs[i]  = g_qkv[base + 1024];
        qfs[i] = g_qf[(size_t)(m0 + n) * 64 + d];
    }
    __syncthreads();
    if (tid < 20) {
        float a = 0.f;
        #pragma unroll 8
        for (int j = 0; j < 64; j++) a += qfs[tid * 64 + j] * Wqp[j * 8 + h];
        av[tid] = a;
    }
    __syncthreads();
    float alpha = *alpha_p, bq = bqp[h];
    for (int t = tid; t < 400; t += 256) {
        int nq = t / 20, nk = t - nq * 20;
        float d = 0.f;
        #pragma unroll 8
        for (int j = 0; j < 64; j++) d += qs[nq * 64 + j] * ks_[nk * 64 + j];
        sc[nq][nk] = d * 0.125f
                   + rel[(nq - nk + 19) * 8 + h]
                   + alpha * gsb[h * 400 + nq * 20 + nk]
                   + (av[nq] - av[nk] + bq);
    }
    __syncthreads();
    if (tid < 20) {
        float mx = -1e30f;
        #pragma unroll
        for (int k = 0; k < 20; k++) mx = fmaxf(mx, sc[tid][k]);
        float s = 0.f;
        #pragma unroll
        for (int k = 0; k < 20; k++) { float e = expf(sc[tid][k] - mx); sc[tid][k] = e; s += e; }
        float inv = 1.f / s;
        #pragma unroll
        for (int k = 0; k < 20; k++) sc[tid][k] *= inv;
    }
    __syncthreads();
    for (int i = tid; i < 1280; i += 256) {
        int nq = i >> 6, d = i & 63;
        float o = 0.f;
        #pragma unroll
        for (int nk = 0; nk < 20; nk++) o += sc[nq][nk] * vs[nk * 64 + d];
        size_t oi = (size_t)(m0 + nq) * Dd + h * 64 + d;
        __nv_bfloat16 hi = __float2bfloat16(o);
        g_att_hi[oi] = hi;
        g_att_lo[oi] = __float2bfloat16(o - __bfloat162float(hi));
    }
}

extern "C" void kernel_launch(void* const* d_in, const int* in_sizes, int n_in,
                              void* d_out, int out_size) {
    const float* x   = (const float*)d_in[0];
    const float* Wq  = (const float*)d_in[1];
    const float* Wk  = (const float*)d_in[2];
    const float* Wv  = (const float*)d_in[3];
    const float* gqg = (const float*)d_in[4];
    const float* gqb = (const float*)d_in[5];
    const float* gkg = (const float*)d_in[6];
    const float* gkb = (const float*)d_in[7];
    const float* gvg = (const float*)d_in[8];
    const float* gvb = (const float*)d_in[9];
    const float* rel = (const float*)d_in[10];
    const float* gsb = (const float*)d_in[11];
    const float* alp = (const float*)d_in[12];
    const float* Wqf = (const float*)d_in[13];
    const float* bqf = (const float*)d_in[14];
    const float* Wqp = (const float*)d_in[15];
    const float* bqp = (const float*)d_in[16];
    const float* Wo  = (const float*)d_in[17];
    const float* bo  = (const float*)d_in[18];
    float* out = (float*)d_out;

    static int inited = 0;
    if (!inited) {
        cudaFuncSetAttribute(mma_gemm<KC, true>,  cudaFuncAttributeMaxDynamicSharedMemorySize, GSMEM);
        cudaFuncSetAttribute(mma_gemm<Dd, false>, cudaFuncAttributeMaxDynamicSharedMemorySize, GSMEM);
        inited = 1;
    }

    x2hl<<<(M_TOT * Dd) / 1024, 256>>>(x);
    pack_w_t<<<(NCP * KC + 255) / 256, 256>>>(Wq, Wk, Wv, Wqf);
    pack_wo_t<<<(Dd * Dd) / 256, 256>>>(Wo);

    dim3 g1(NCP / 128, M_TOT / 128);   // 13 x 320
    mma_gemm<KC, true><<<g1, 256, GSMEM>>>(nullptr, nullptr, bqf);

    dim3 g2(M_TOT, 3);
    ln_res<<<g2, 128>>>(x, gqg, gqb, gkg, gkb, gvg, gvb);

    attn_kernel<<<Bsz * Hh, 256>>>(rel, gsb, alp, Wqp, bqp);

    dim3 g3(Dd / 128, M_TOT / 128);    // 4 x 320
    mma_gemm<Dd, false><<<g3, 256, GSMEM>>>(out, bo, nullptr);
}

// round 4
// speedup vs baseline: 3.3926x; 1.3650x over previous
#include <cuda_runtime.h>
#include <cuda_fp16.h>
#include <math.h>
#include <stdint.h>

#define Bsz 2048
#define Nn  20
#define Dd  512
#define Hh  8
#define M_TOT (Bsz*Nn)   // 40960
#define KC 1536          // conv GEMM K
#define NC 1536          // q|k|v cols
#define NCP 1664         // 1536 qkv + 64 qf + 64 zero = 13*128

// ---------------- device scratch ----------------
__device__ __half g_x_h[(size_t)M_TOT * Dd];
__device__ __half g_wpt_hi[(size_t)NCP * KC];
__device__ __half g_wpt_lo[(size_t)NCP * KC];
__device__ __half g_wot_hi[(size_t)Dd * Dd];
__device__ __half g_wot_lo[(size_t)Dd * Dd];
__device__ float g_qkv[(size_t)M_TOT * NC];
__device__ float g_qf[(size_t)M_TOT * 64];
__device__ __half g_att_h[(size_t)M_TOT * Dd];

// ---------------- helpers ----------------
__device__ __forceinline__ uint32_t smem_u32(const void* p) {
    uint32_t a;
    asm("{ .reg .u64 t; cvta.to.shared.u64 t, %1; cvt.u32.u64 %0, t; }" : "=r"(a) : "l"(p));
    return a;
}
#define LDSM4(r, addr) \
    asm volatile("ldmatrix.sync.aligned.m8n8.x4.shared.b16 {%0,%1,%2,%3}, [%4];" \
        : "=r"((r)[0]), "=r"((r)[1]), "=r"((r)[2]), "=r"((r)[3]) : "r"(addr))

__device__ __forceinline__ void mma16816(float* d, const uint32_t* a, const uint32_t* b) {
    asm volatile(
        "mma.sync.aligned.m16n8k16.row.col.f32.f16.f16.f32 "
        "{%0,%1,%2,%3}, {%4,%5,%6,%7}, {%8,%9}, {%0,%1,%2,%3};"
        : "+f"(d[0]), "+f"(d[1]), "+f"(d[2]), "+f"(d[3])
        : "r"(a[0]), "r"(a[1]), "r"(a[2]), "r"(a[3]), "r"(b[0]), "r"(b[1]));
}
__device__ __forceinline__ void cp16(uint32_t dst, const void* src, uint32_t sz) {
    asm volatile("cp.async.cg.shared.global [%0], [%1], 16, %2;" :: "r"(dst), "l"(src), "r"(sz) : "memory");
}
#define CP_COMMIT() asm volatile("cp.async.commit_group;" ::: "memory")
#define CP_WAIT1()  asm volatile("cp.async.wait_group 1;" ::: "memory")
#define CP_WAIT0()  asm volatile("cp.async.wait_group 0;" ::: "memory")

// ---------------- conversions / packing ----------------
__global__ void x2h(const float* __restrict__ x) {
    size_t i = (size_t)(blockIdx.x * blockDim.x + threadIdx.x) * 4;
    #pragma unroll
    for (int u = 0; u < 4; u++) g_x_h[i + u] = __float2half_rn(x[i + u]);
}

__global__ void pack_w_t(const float* __restrict__ Wq, const float* __restrict__ Wk,
                         const float* __restrict__ Wv, const float* __restrict__ Wqf) {
    int idx = blockIdx.x * blockDim.x + threadIdx.x;
    if (idx >= NCP * KC) return;
    int j = idx / KC, k = idx - (idx / KC) * KC;
    float w = 0.f;
    if (j < NC) {
        int p = j >> 9, o = j & 511;
        int s = k >> 9, i = k & 511;
        const float* W = (p == 0) ? Wq : (p == 1 ? Wk : Wv);
        w = W[(o * Dd + i) * 3 + s];
    } else if (j < NC + 64) {
        int jj = j - NC;
        if ((k >> 9) == 1) w = Wqf[(k & 511) * 64 + jj];
    }
    __half hi = __float2half_rn(w);
    g_wpt_hi[(size_t)j * KC + k] = hi;
    g_wpt_lo[(size_t)j * KC + k] = __float2half_rn(w - __half2float(hi));
}

__global__ void pack_wo_t(const float* __restrict__ Wo) {
    int idx = blockIdx.x * blockDim.x + threadIdx.x;
    int j = idx >> 9, k = idx & 511;
    float w = Wo[(size_t)k * Dd + j];
    __half hi = __float2half_rn(w);
    g_wot_hi[(size_t)j * Dd + k] = hi;
    g_wot_lo[(size_t)j * Dd + k] = __float2half_rn(w - __half2float(hi));
}

// ---------------- mma.sync GEMM: 128x128 tiles, K=32 double-buffered ----------------
// stage: 3 matrices (Ah, Bh, Bl), each 128 rows x 40 fp16 (32 used + 8 pad)
#define ROWP 40
#define MATB (128 * ROWP * 2)          // 10240 B
#define STAGE_B (3 * MATB)             // 30720 B
#define GSMEM (2 * STAGE_B)            // 61440 B

template<int KDIM, bool CONV>
__global__ __launch_bounds__(256, 2) void mma_gemm(float* __restrict__ Cout,
                                                   const float* __restrict__ bias,
                                                   const float* __restrict__ bqf) {
    extern __shared__ char smc[];
    const uint32_t sbase = smem_u32(smc);
    const int tid = threadIdx.x;
    const int bm = blockIdx.y * 128, bn = blockIdx.x * 128;
    const int NCH = KDIM / 32;

    const __half* Ah  = CONV ? g_x_h : g_att_h;
    const __half* Bhi = CONV ? g_wpt_hi : g_wot_hi;
    const __half* Blo = CONV ? g_wpt_lo : g_wot_lo;

    auto load_stage = [&](int c) {
        const int k0 = c * 32;
        const uint32_t sb = sbase + (c & 1) * STAGE_B;
        #pragma unroll
        for (int i = 0; i < 6; i++) {
            int t = tid + i * 256;
            int mat = t >> 9, idx = t & 511, row = idx >> 2, q = idx & 3;
            uint32_t dst = sb + mat * MATB + (row * ROWP + q * 8) * 2;
            const __half* src;
            uint32_t sz = 16;
            if (mat == 0) {
                if (CONV) {
                    int m = bm + row;
                    int b = m / Nn, n = m - b * Nn;
                    int sn = n + (k0 >> 9) - 1;
                    int snc = sn < 0 ? 0 : (sn >= Nn ? Nn - 1 : sn);
                    if (sn != snc) sz = 0;
                    src = Ah + (((size_t)(b * Nn + snc)) << 9) + (k0 & 511) + q * 8;
                } else {
                    src = Ah + (size_t)(bm + row) * KDIM + k0 + q * 8;
                }
            } else {
                const __half* base = (mat == 1) ? Bhi : Blo;
                src = base + (size_t)(bn + row) * KDIM + k0 + q * 8;
            }
            cp16(dst, src, sz);
        }
        CP_COMMIT();
    };

    const int lane = tid & 31, wid = tid >> 5;
    const int wm = (wid >> 2) * 64, wn = (wid & 3) * 32;
    float acc[4][4][4];
    #pragma unroll
    for (int a = 0; a < 4; a++)
        #pragma unroll
        for (int b = 0; b < 4; b++)
            #pragma unroll
            for (int d = 0; d < 4; d++) acc[a][b][d] = 0.f;

    load_stage(0);

    for (int c = 0; c < NCH; c++) {
        if (c + 1 < NCH) { load_stage(c + 1); CP_WAIT1(); }
        else             { CP_WAIT0(); }
        __syncthreads();
        const uint32_t sb = sbase + (c & 1) * STAGE_B;
        #pragma unroll
        for (int kk = 0; kk < 2; kk++) {
            const int koff = kk * 16 + ((lane >> 4) << 3);
            const int arow = lane & 15;
            uint32_t a_h[4][4], b_h[4][2], b_l[4][2];
            #pragma unroll
            for (int mt = 0; mt < 4; mt++) {
                uint32_t ad = sb + ((wm + mt * 16 + arow) * ROWP + koff) * 2;
                LDSM4(a_h[mt], ad);
            }
            const int brow = ((lane >> 4) << 3) + (lane & 7);
            const int bkoff = kk * 16 + (((lane >> 3) & 1) << 3);
            #pragma unroll
            for (int pr = 0; pr < 2; pr++) {
                uint32_t bd = sb + MATB + ((wn + pr * 16 + brow) * ROWP + bkoff) * 2;
                uint32_t r[4];
                LDSM4(r, bd);
                b_h[pr * 2][0] = r[0]; b_h[pr * 2][1] = r[1];
                b_h[pr * 2 + 1][0] = r[2]; b_h[pr * 2 + 1][1] = r[3];
                LDSM4(r, bd + MATB);
                b_l[pr * 2][0] = r[0]; b_l[pr * 2][1] = r[1];
                b_l[pr * 2 + 1][0] = r[2]; b_l[pr * 2 + 1][1] = r[3];
            }
            #pragma unroll
            for (int mt = 0; mt < 4; mt++)
                #pragma unroll
                for (int nt = 0; nt < 4; nt++) {
                    mma16816(acc[mt][nt], a_h[mt], b_h[nt]);
                    mma16816(acc[mt][nt], a_h[mt], b_l[nt]);
                }
        }
        __syncthreads();
    }

    // ---------------- epilogue ----------------
    const int g = lane >> 2, tg = lane & 3;
    #pragma unroll
    for (int mt = 0; mt < 4; mt++) {
        #pragma unroll
        for (int nt = 0; nt < 4; nt++) {
            int j = bn + wn + nt * 8 + tg * 2;
            #pragma unroll
            for (int half = 0; half < 2; half++) {
                int m = bm + wm + mt * 16 + g + half * 8;
                float d0 = acc[mt][nt][half * 2], d1 = acc[mt][nt][half * 2 + 1];
                if (CONV) {
                    if (j < NC) {
                        *(float2*)(g_qkv + (size_t)m * NC + j) = make_float2(d0, d1);
                    } else if (j < NC + 64) {
                        int jj = j - NC;
                        *(float2*)(g_qf + (size_t)m * 64 + jj) =
                            make_float2(tanhf(d0 + bqf[jj]), tanhf(d1 + bqf[jj + 1]));
                    }
                } else {
                    *(float2*)(Cout + (size_t)m * KDIM + j) =
                        make_float2(d0 + bias[j], d1 + bias[j + 1]);
                }
            }
        }
    }
}

// ---------------- fused LN + residual + attention, one block per batch b ----------------
#define QSTRIDE 1537
#define SM_QKV 0
#define SM_QF  (20 * QSTRIDE)                 // 30740
#define SM_SC  (SM_QF + 20 * 64)              // 32020
#define SM_AV  (SM_SC + 8 * 400)              // 35220
#define SM_FLT (SM_AV + 160)                  // 35380
#define ASMEM  (SM_FLT * 4)                   // 141520 B

__global__ __launch_bounds__(256) void ln_attn(const float* __restrict__ x,
                                               const float* __restrict__ g0, const float* __restrict__ b0,
                                               const float* __restrict__ g1, const float* __restrict__ b1,
                                               const float* __restrict__ g2, const float* __restrict__ b2,
                                               const float* __restrict__ rel,
                                               const float* __restrict__ gsb,
                                               const float* __restrict__ alpha_p,
                                               const float* __restrict__ Wqp,
                                               const float* __restrict__ bqp) {
    extern __shared__ float sm[];
    const int b = blockIdx.x;
    const int tid = threadIdx.x, lane = tid & 31, wid = tid >> 5;
    const size_t row0 = (size_t)b * Nn;

    // load conv output (pre-LN) and qf
    for (int i = tid; i < 20 * 1536; i += 256) {
        int n = i / 1536, j = i - n * 1536;
        sm[SM_QKV + n * QSTRIDE + j] = g_qkv[(row0 + n) * NC + j];
    }
    for (int i = tid; i < 1280; i += 256)
        sm[SM_QF + i] = g_qf[row0 * 64 + i];
    __syncthreads();

    // LN + residual, 60 segments (n, p)
    for (int seg = wid; seg < 60; seg += 8) {
        int n = seg / 3, p = seg - n * 3;
        float* base = sm + SM_QKV + n * QSTRIDE + p * 512;
        const float* g  = (p == 0) ? g0 : (p == 1 ? g1 : g2);
        const float* bb = (p == 0) ? b0 : (p == 1 ? b1 : b2);
        float v[16], s = 0.f, s2 = 0.f;
        #pragma unroll
        for (int i = 0; i < 16; i++) {
            v[i] = base[i * 32 + lane];
            s += v[i]; s2 += v[i] * v[i];
        }
        #pragma unroll
        for (int o = 16; o; o >>= 1) {
            s  += __shfl_xor_sync(0xffffffffu, s, o);
            s2 += __shfl_xor_sync(0xffffffffu, s2, o);
        }
        float mean = s * (1.f / 512.f);
        float inv = rsqrtf(s2 * (1.f / 512.f) - mean * mean + 1e-5f);
        const float* xr = x + (row0 + n) * Dd;
        #pragma unroll
        for (int i = 0; i < 16; i++) {
            int c = i * 32 + lane;
            base[c] = xr[c] + (v[i] - mean) * inv * g[c] + bb[c];
        }
    }
    __syncthreads();

    // dynamic bias av[n][h]
    if (tid < 160) {
        int n = tid >> 3, h = tid & 7;
        float a = 0.f;
        #pragma unroll 8
        for (int j = 0; j < 64; j++) a += sm[SM_QF + n * 64 + j] * Wqp[j * 8 + h];
        sm[SM_AV + tid] = a;
    }
    __syncthreads();

    const float alpha = *alpha_p;
    // scores
    for (int t = tid; t < 3200; t += 256) {
        int h = t / 400, r = t - h * 400;
        int nq = r / 20, nk = r - nq * 20;
        const float* q = sm + SM_QKV + nq * QSTRIDE + h * 64;
        const float* k = sm + SM_QKV + nk * QSTRIDE + 512 + h * 64;
        float d = 0.f;
        #pragma unroll 8
        for (int j = 0; j < 64; j++) d += q[j] * k[j];
        sm[SM_SC + t] = d * 0.125f
                      + rel[(nq - nk + 19) * 8 + h]
                      + alpha * gsb[h * 400 + nq * 20 + nk]
                      + (sm[SM_AV + nq * 8 + h] - sm[SM_AV + nk * 8 + h] + bqp[h]);
    }
    __syncthreads();

    // softmax over nk, 160 rows
    if (tid < 160) {
        float* row = sm + SM_SC + tid * 20;
        float mx = -1e30f;
        #pragma unroll
        for (int k = 0; k < 20; k++) mx = fmaxf(mx, row[k]);
        float s = 0.f;
        #pragma unroll
        for (int k = 0; k < 20; k++) { float e = expf(row[k] - mx); row[k] = e; s += e; }
        float inv = 1.f / s;
        #pragma unroll
        for (int k = 0; k < 20; k++) row[k] *= inv;
    }
    __syncthreads();

    // out = attn @ v, write fp16
    for (int i = tid; i < 10240; i += 256) {
        int n = i >> 9, c = i & 511;
        int h = c >> 6, d = c & 63;
        const float* a = sm + SM_SC + (h * 20 + n) * 20;
        float o = 0.f;
        #pragma unroll
        for (int nk = 0; nk < 20; nk++)
            o += a[nk] * sm[SM_QKV + nk * QSTRIDE + 1024 + h * 64 + d];
        g_att_h[(row0 + n) * Dd + c] = __float2half_rn(o);
    }
}

extern "C" void kernel_launch(void* const* d_in, const int* in_sizes, int n_in,
                              void* d_out, int out_size) {
    const float* x   = (const float*)d_in[0];
    const float* Wq  = (const float*)d_in[1];
    const float* Wk  = (const float*)d_in[2];
    const float* Wv  = (const float*)d_in[3];
    const float* gqg = (const float*)d_in[4];
    const float* gqb = (const float*)d_in[5];
    const float* gkg = (const float*)d_in[6];
    const float* gkb = (const float*)d_in[7];
    const float* gvg = (const float*)d_in[8];
    const float* gvb = (const float*)d_in[9];
    const float* rel = (const float*)d_in[10];
    const float* gsb = (const float*)d_in[11];
    const float* alp = (const float*)d_in[12];
    const float* Wqf = (const float*)d_in[13];
    const float* bqf = (const float*)d_in[14];
    const float* Wqp = (const float*)d_in[15];
    const float* bqp = (const float*)d_in[16];
    const float* Wo  = (const float*)d_in[17];
    const float* bo  = (const float*)d_in[18];
    float* out = (float*)d_out;

    static int inited = 0;
    if (!inited) {
        cudaFuncSetAttribute(mma_gemm<KC, true>,  cudaFuncAttributeMaxDynamicSharedMemorySize, GSMEM);
        cudaFuncSetAttribute(mma_gemm<Dd, false>, cudaFuncAttributeMaxDynamicSharedMemorySize, GSMEM);
        cudaFuncSetAttribute(ln_attn, cudaFuncAttributeMaxDynamicSharedMemorySize, ASMEM);
        inited = 1;
    }

    x2h<<<(M_TOT * Dd) / 1024, 256>>>(x);
    pack_w_t<<<(NCP * KC + 255) / 256, 256>>>(Wq, Wk, Wv, Wqf);
    pack_wo_t<<<(Dd * Dd) / 256, 256>>>(Wo);

    dim3 g1(NCP / 128, M_TOT / 128);   // 13 x 320
    mma_gemm<KC, true><<<g1, 256, GSMEM>>>(nullptr, nullptr, bqf);

    ln_attn<<<Bsz, 256, ASMEM>>>(x, gqg, gqb, gkg, gkb, gvg, gvb,
                                 rel, gsb, alp, Wqp, bqp);

    dim3 g3(Dd / 128, M_TOT / 128);    // 4 x 320
    mma_gemm<Dd, false><<<g3, 256, GSMEM>>>(out, bo, nullptr);
}

// round 7
// speedup vs baseline: 4.7174x; 1.3905x over previous
#include <cuda_runtime.h>
#include <cuda_fp16.h>
#include <math.h>
#include <stdint.h>

#define Bsz 2048
#define Nn  20
#define Dd  512
#define Hh  8
#define M_TOT (Bsz*Nn)   // 40960
#define KC 1536          // conv GEMM K
#define NC 1536          // q|k|v cols
#define NCP 1664         // 1536 qkv + 64 qf + 64 zero = 13*128

// ---------------- device scratch ----------------
__device__ __half g_x_h[(size_t)M_TOT * Dd];
__device__ __half g_wpt[(size_t)NCP * KC];
__device__ __half g_wot[(size_t)Dd * Dd];
__device__ float g_qkv[(size_t)M_TOT * NC];
__device__ float g_qf[(size_t)M_TOT * 64];
__device__ __half g_att_h[(size_t)M_TOT * Dd];

// ---------------- helpers ----------------
__device__ __forceinline__ uint32_t smem_u32(const void* p) {
    uint32_t a;
    asm("{ .reg .u64 t; cvta.to.shared.u64 t, %1; cvt.u32.u64 %0, t; }" : "=r"(a) : "l"(p));
    return a;
}
#define LDSM4(r, addr) \
    asm volatile("ldmatrix.sync.aligned.m8n8.x4.shared.b16 {%0,%1,%2,%3}, [%4];" \
        : "=r"((r)[0]), "=r"((r)[1]), "=r"((r)[2]), "=r"((r)[3]) : "r"(addr))

__device__ __forceinline__ void mma16816(float* d, const uint32_t* a, const uint32_t* b) {
    asm volatile(
        "mma.sync.aligned.m16n8k16.row.col.f32.f16.f16.f32 "
        "{%0,%1,%2,%3}, {%4,%5,%6,%7}, {%8,%9}, {%0,%1,%2,%3};"
        : "+f"(d[0]), "+f"(d[1]), "+f"(d[2]), "+f"(d[3])
        : "r"(a[0]), "r"(a[1]), "r"(a[2]), "r"(a[3]), "r"(b[0]), "r"(b[1]));
}
__device__ __forceinline__ void cp16(uint32_t dst, const void* src, uint32_t sz) {
    asm volatile("cp.async.cg.shared.global [%0], [%1], 16, %2;" :: "r"(dst), "l"(src), "r"(sz) : "memory");
}
#define CP_COMMIT() asm volatile("cp.async.commit_group;" ::: "memory")

// ---------------- conversions / packing ----------------
__global__ void x2h(const float* __restrict__ x) {
    size_t i = (size_t)(blockIdx.x * blockDim.x + threadIdx.x);
    float4 v = ((const float4*)x)[i];
    __half2* o = (__half2*)g_x_h;
    o[i * 2]     = __floats2half2_rn(v.x, v.y);
    o[i * 2 + 1] = __floats2half2_rn(v.z, v.w);
}

__global__ void pack_w_t(const float* __restrict__ Wq, const float* __restrict__ Wk,
                         const float* __restrict__ Wv, const float* __restrict__ Wqf) {
    int idx = blockIdx.x * blockDim.x + threadIdx.x;
    if (idx >= NCP * KC) return;
    int j = idx / KC, k = idx - (idx / KC) * KC;
    float w = 0.f;
    if (j < NC) {
        int p = j >> 9, o = j & 511;
        int s = k >> 9, i = k & 511;
        const float* W = (p == 0) ? Wq : (p == 1 ? Wk : Wv);
        w = W[(o * Dd + i) * 3 + s];
    } else if (j < NC + 64) {
        int jj = j - NC;
        if ((k >> 9) == 1) w = Wqf[(k & 511) * 64 + jj];
    }
    g_wpt[(size_t)j * KC + k] = __float2half_rn(w);
}

__global__ void pack_wo_t(const float* __restrict__ Wo) {
    int idx = blockIdx.x * blockDim.x + threadIdx.x;
    int j = idx >> 9, k = idx & 511;
    g_wot[(size_t)j * Dd + k] = __float2half_rn(Wo[(size_t)k * Dd + j]);
}

// ---------------- mma.sync GEMM: 128x128 tiles, K=32, 4-stage cp.async ----------------
// stage: 2 matrices (A, B), each 128 rows x 40 fp16 (32 used + 8 pad)
#define ROWP 40
#define MATB (128 * ROWP * 2)          // 10240 B
#define STAGE_B (2 * MATB)             // 20480 B
#define GSMEM (4 * STAGE_B)            // 81920 B

template<int KDIM, bool CONV>
__global__ __launch_bounds__(256, 2) void mma_gemm(float* __restrict__ Cout,
                                                   const float* __restrict__ bias,
                                                   const float* __restrict__ bqf) {
    extern __shared__ char smc[];
    const uint32_t sbase = smem_u32(smc);
    const int tid = threadIdx.x;
    const int bm = blockIdx.y * 128, bn = blockIdx.x * 128;
    const int NCH = KDIM / 32;

    const __half* Ah = CONV ? g_x_h : g_att_h;
    const __half* Bh = CONV ? g_wpt : g_wot;

    auto load_stage = [&](int c) {
        const int k0 = c * 32;
        const uint32_t sb = sbase + (c & 3) * STAGE_B;
        #pragma unroll
        for (int i = 0; i < 4; i++) {
            int t = tid + i * 256;
            int mat = t >> 9, idx = t & 511, row = idx >> 2, q = idx & 3;
            uint32_t dst = sb + mat * MATB + (row * ROWP + q * 8) * 2;
            const __half* src;
            uint32_t sz = 16;
            if (mat == 0) {
                if (CONV) {
                    int m = bm + row;
                    int b = m / Nn, n = m - b * Nn;
                    int sn = n + (k0 >> 9) - 1;
                    int snc = sn < 0 ? 0 : (sn >= Nn ? Nn - 1 : sn);
                    if (sn != snc) sz = 0;
                    src = Ah + (((size_t)(b * Nn + snc)) << 9) + (k0 & 511) + q * 8;
                } else {
                    src = Ah + (size_t)(bm + row) * KDIM + k0 + q * 8;
                }
            } else {
                src = Bh + (size_t)(bn + row) * KDIM + k0 + q * 8;
            }
            cp16(dst, src, sz);
        }
        CP_COMMIT();
    };

    const int lane = tid & 31, wid = tid >> 5;
    const int wm = (wid >> 2) * 64, wn = (wid & 3) * 32;
    float acc[4][4][4];
    #pragma unroll
    for (int a = 0; a < 4; a++)
        #pragma unroll
        for (int b = 0; b < 4; b++)
            #pragma unroll
            for (int d = 0; d < 4; d++) acc[a][b][d] = 0.f;

    load_stage(0); load_stage(1); load_stage(2);

    for (int c = 0; c < NCH; c++) {
        if (c + 3 < NCH) {
            load_stage(c + 3);
            asm volatile("cp.async.wait_group 3;" ::: "memory");
        } else if (c + 2 < NCH) {
            asm volatile("cp.async.wait_group 2;" ::: "memory");
        } else if (c + 1 < NCH) {
            asm volatile("cp.async.wait_group 1;" ::: "memory");
        } else {
            asm volatile("cp.async.wait_group 0;" ::: "memory");
        }
        __syncthreads();
        const uint32_t sb = sbase + (c & 3) * STAGE_B;
        #pragma unroll
        for (int kk = 0; kk < 2; kk++) {
            const int koff = kk * 16 + ((lane >> 4) << 3);
            const int arow = lane & 15;
            uint32_t a_h[4][4], b_h[4][2];
            #pragma unroll
            for (int mt = 0; mt < 4; mt++) {
                uint32_t ad = sb + ((wm + mt * 16 + arow) * ROWP + koff) * 2;
                LDSM4(a_h[mt], ad);
            }
            const int brow = ((lane >> 4) << 3) + (lane & 7);
            const int bkoff = kk * 16 + (((lane >> 3) & 1) << 3);
            #pragma unroll
            for (int pr = 0; pr < 2; pr++) {
                uint32_t bd = sb + MATB + ((wn + pr * 16 + brow) * ROWP + bkoff) * 2;
                uint32_t r[4];
                LDSM4(r, bd);
                b_h[pr * 2][0] = r[0]; b_h[pr * 2][1] = r[1];
                b_h[pr * 2 + 1][0] = r[2]; b_h[pr * 2 + 1][1] = r[3];
            }
            #pragma unroll
            for (int mt = 0; mt < 4; mt++)
                #pragma unroll
                for (int nt = 0; nt < 4; nt++)
                    mma16816(acc[mt][nt], a_h[mt], b_h[nt]);
        }
        __syncthreads();
    }

    // ---------------- epilogue ----------------
    const int g = lane >> 2, tg = lane & 3;
    #pragma unroll
    for (int mt = 0; mt < 4; mt++) {
        #pragma unroll
        for (int nt = 0; nt < 4; nt++) {
            int j = bn + wn + nt * 8 + tg * 2;
            #pragma unroll
            for (int half = 0; half < 2; half++) {
                int m = bm + wm + mt * 16 + g + half * 8;
                float d0 = acc[mt][nt][half * 2], d1 = acc[mt][nt][half * 2 + 1];
                if (CONV) {
                    if (j < NC) {
                        *(float2*)(g_qkv + (size_t)m * NC + j) = make_float2(d0, d1);
                    } else if (j < NC + 64) {
                        int jj = j - NC;
                        *(float2*)(g_qf + (size_t)m * 64 + jj) =
                            make_float2(tanhf(d0 + bqf[jj]), tanhf(d1 + bqf[jj + 1]));
                    }
                } else {
                    *(float2*)(Cout + (size_t)m * KDIM + j) =
                        make_float2(d0 + bias[j], d1 + bias[j + 1]);
                }
            }
        }
    }
}

// ---------------- fused LN + residual + attention, one block per batch b ----------------
#define QSTRIDE 1537
#define SM_QKV 0
#define SM_QF  (20 * QSTRIDE)                 // 30740
#define SM_SC  (SM_QF + 20 * 64)              // 32020
#define SM_AV  (SM_SC + 8 * 400)              // 35220
#define SM_FLT (SM_AV + 160)                  // 35380
#define ASMEM  (SM_FLT * 4)                   // 141520 B

__global__ __launch_bounds__(256) void ln_attn(const float* __restrict__ x,
                                               const float* __restrict__ g0, const float* __restrict__ b0,
                                               const float* __restrict__ g1, const float* __restrict__ b1,
                                               const float* __restrict__ g2, const float* __restrict__ b2,
                                               const float* __restrict__ rel,
                                               const float* __restrict__ gsb,
                                               const float* __restrict__ alpha_p,
                                               const float* __restrict__ Wqp,
                                               const float* __restrict__ bqp) {
    extern __shared__ float sm[];
    const int b = blockIdx.x;
    const int tid = threadIdx.x, lane = tid & 31, wid = tid >> 5;
    const size_t row0 = (size_t)b * Nn;

    for (int i = tid; i < 20 * 1536; i += 256) {
        int n = i / 1536, j = i - n * 1536;
        sm[SM_QKV + n * QSTRIDE + j] = g_qkv[(row0 + n) * NC + j];
    }
    for (int i = tid; i < 1280; i += 256)
        sm[SM_QF + i] = g_qf[row0 * 64 + i];
    __syncthreads();

    for (int seg = wid; seg < 60; seg += 8) {
        int n = seg / 3, p = seg - n * 3;
        float* base = sm + SM_QKV + n * QSTRIDE + p * 512;
        const float* g  = (p == 0) ? g0 : (p == 1 ? g1 : g2);
        const float* bb = (p == 0) ? b0 : (p == 1 ? b1 : b2);
        float v[16], s = 0.f, s2 = 0.f;
        #pragma unroll
        for (int i = 0; i < 16; i++) {
            v[i] = base[i * 32 + lane];
            s += v[i]; s2 += v[i] * v[i];
        }
        #pragma unroll
        for (int o = 16; o; o >>= 1) {
            s  += __shfl_xor_sync(0xffffffffu, s, o);
            s2 += __shfl_xor_sync(0xffffffffu, s2, o);
        }
        float mean = s * (1.f / 512.f);
        float inv = rsqrtf(s2 * (1.f / 512.f) - mean * mean + 1e-5f);
        const float* xr = x + (row0 + n) * Dd;
        #pragma unroll
        for (int i = 0; i < 16; i++) {
            int c = i * 32 + lane;
            base[c] = xr[c] + (v[i] - mean) * inv * g[c] + bb[c];
        }
    }
    __syncthreads();

    if (tid < 160) {
        int n = tid >> 3, h = tid & 7;
        float a = 0.f;
        #pragma unroll 8
        for (int j = 0; j < 64; j++) a += sm[SM_QF + n * 64 + j] * Wqp[j * 8 + h];
        sm[SM_AV + tid] = a;
    }
    __syncthreads();

    const float alpha = *alpha_p;
    for (int t = tid; t < 3200; t += 256) {
        int h = t / 400, r = t - h * 400;
        int nq = r / 20, nk = r - nq * 20;
        const float* q = sm + SM_QKV + nq * QSTRIDE + h * 64;
        const float* k = sm + SM_QKV + nk * QSTRIDE + 512 + h * 64;
        float d = 0.f;
        #pragma unroll 8
        for (int j = 0; j < 64; j++) d += q[j] * k[j];
        sm[SM_SC + t] = d * 0.125f
                      + rel[(nq - nk + 19) * 8 + h]
                      + alpha * gsb[h * 400 + nq * 20 + nk]
                      + (sm[SM_AV + nq * 8 + h] - sm[SM_AV + nk * 8 + h] + bqp[h]);
    }
    __syncthreads();

    if (tid < 160) {
        float* row = sm + SM_SC + tid * 20;
        float mx = -1e30f;
        #pragma unroll
        for (int k = 0; k < 20; k++) mx = fmaxf(mx, row[k]);
        float s = 0.f;
        #pragma unroll
        for (int k = 0; k < 20; k++) { float e = expf(row[k] - mx); row[k] = e; s += e; }
        float inv = 1.f / s;
        #pragma unroll
        for (int k = 0; k < 20; k++) row[k] *= inv;
    }
    __syncthreads();

    for (int i = tid; i < 10240; i += 256) {
        int n = i >> 9, c = i & 511;
        int h = c >> 6, d = c & 63;
        const float* a = sm + SM_SC + (h * 20 + n) * 20;
        float o = 0.f;
        #pragma unroll
        for (int nk = 0; nk < 20; nk++)
            o += a[nk] * sm[SM_QKV + nk * QSTRIDE + 1024 + h * 64 + d];
        g_att_h[(row0 + n) * Dd + c] = __float2half_rn(o);
    }
}

extern "C" void kernel_launch(void* const* d_in, const int* in_sizes, int n_in,
                              void* d_out, int out_size) {
    const float* x   = (const float*)d_in[0];
    const float* Wq  = (const float*)d_in[1];
    const float* Wk  = (const float*)d_in[2];
    const float* Wv  = (const float*)d_in[3];
    const float* gqg = (const float*)d_in[4];
    const float* gqb = (const float*)d_in[5];
    const float* gkg = (const float*)d_in[6];
    const float* gkb = (const float*)d_in[7];
    const float* gvg = (const float*)d_in[8];
    const float* gvb = (const float*)d_in[9];
    const float* rel = (const float*)d_in[10];
    const float* gsb = (const float*)d_in[11];
    const float* alp = (const float*)d_in[12];
    const float* Wqf = (const float*)d_in[13];
    const float* bqf = (const float*)d_in[14];
    const float* Wqp = (const float*)d_in[15];
    const float* bqp = (const float*)d_in[16];
    const float* Wo  = (const float*)d_in[17];
    const float* bo  = (const float*)d_in[18];
    float* out = (float*)d_out;

    static int inited = 0;
    if (!inited) {
        cudaFuncSetAttribute(mma_gemm<KC, true>,  cudaFuncAttributeMaxDynamicSharedMemorySize, GSMEM);
        cudaFuncSetAttribute(mma_gemm<Dd, false>, cudaFuncAttributeMaxDynamicSharedMemorySize, GSMEM);
        cudaFuncSetAttribute(ln_attn, cudaFuncAttributeMaxDynamicSharedMemorySize, ASMEM);
        inited = 1;
    }

    x2h<<<(M_TOT * Dd) / 1024, 256>>>(x);
    pack_w_t<<<(NCP * KC + 255) / 256, 256>>>(Wq, Wk, Wv, Wqf);
    pack_wo_t<<<(Dd * Dd) / 256, 256>>>(Wo);

    dim3 g1(NCP / 128, M_TOT / 128);   // 13 x 320
    mma_gemm<KC, true><<<g1, 256, GSMEM>>>(nullptr, nullptr, bqf);

    ln_attn<<<Bsz, 256, ASMEM>>>(x, gqg, gqb, gkg, gkb, gvg, gvb,
                                 rel, gsb, alp, Wqp, bqp);

    dim3 g3(Dd / 128, M_TOT / 128);    // 4 x 320
    mma_gemm<Dd, false><<<g3, 256, GSMEM>>>(out, bo, nullptr);
}

// round 8
// speedup vs baseline: 6.7237x; 1.4253x over previous
#include <cuda_runtime.h>
#include <cuda_fp16.h>
#include <math.h>
#include <stdint.h>

#define Bsz 2048
#define Nn  20
#define Dd  512
#define Hh  8
#define M_TOT (Bsz*Nn)   // 40960
#define KC 1536          // conv GEMM K
#define NC 1536          // q|k|v cols
#define NCP 1664         // 1536 qkv + 64 qf + 64 zero = 13*128

// ---------------- device scratch ----------------
__device__ __half g_x_h[(size_t)M_TOT * Dd];
__device__ __half g_wpt[(size_t)NCP * KC];
__device__ __half g_wot[(size_t)Dd * Dd];
__device__ float g_qkv[(size_t)M_TOT * NC];
__device__ float g_qf[(size_t)M_TOT * 64];
__device__ __half g_att_h[(size_t)M_TOT * Dd];

// ---------------- helpers ----------------
__device__ __forceinline__ uint32_t smem_u32(const void* p) {
    uint32_t a;
    asm("{ .reg .u64 t; cvta.to.shared.u64 t, %1; cvt.u32.u64 %0, t; }" : "=r"(a) : "l"(p));
    return a;
}
#define LDSM4(r, addr) \
    asm volatile("ldmatrix.sync.aligned.m8n8.x4.shared.b16 {%0,%1,%2,%3}, [%4];" \
        : "=r"((r)[0]), "=r"((r)[1]), "=r"((r)[2]), "=r"((r)[3]) : "r"(addr))

__device__ __forceinline__ void mma16816(float* d, const uint32_t* a, const uint32_t* b) {
    asm volatile(
        "mma.sync.aligned.m16n8k16.row.col.f32.f16.f16.f32 "
        "{%0,%1,%2,%3}, {%4,%5,%6,%7}, {%8,%9}, {%0,%1,%2,%3};"
        : "+f"(d[0]), "+f"(d[1]), "+f"(d[2]), "+f"(d[3])
        : "r"(a[0]), "r"(a[1]), "r"(a[2]), "r"(a[3]), "r"(b[0]), "r"(b[1]));
}
__device__ __forceinline__ void cp16(uint32_t dst, const void* src, uint32_t sz) {
    asm volatile("cp.async.cg.shared.global [%0], [%1], 16, %2;" :: "r"(dst), "l"(src), "r"(sz) : "memory");
}
#define CP_COMMIT() asm volatile("cp.async.commit_group;" ::: "memory")

// ---------------- conversions / packing ----------------
__global__ void x2h(const float* __restrict__ x) {
    size_t i = (size_t)(blockIdx.x * blockDim.x + threadIdx.x);
    float4 v = ((const float4*)x)[i];
    __half2* o = (__half2*)g_x_h;
    o[i * 2]     = __floats2half2_rn(v.x, v.y);
    o[i * 2 + 1] = __floats2half2_rn(v.z, v.w);
}

__global__ void pack_w_t(const float* __restrict__ Wq, const float* __restrict__ Wk,
                         const float* __restrict__ Wv, const float* __restrict__ Wqf) {
    int idx = blockIdx.x * blockDim.x + threadIdx.x;
    if (idx >= NCP * KC) return;
    int j = idx / KC, k = idx - (idx / KC) * KC;
    float w = 0.f;
    if (j < NC) {
        int p = j >> 9, o = j & 511;
        int s = k >> 9, i = k & 511;
        const float* W = (p == 0) ? Wq : (p == 1 ? Wk : Wv);
        w = W[(o * Dd + i) * 3 + s];
    } else if (j < NC + 64) {
        int jj = j - NC;
        if ((k >> 9) == 1) w = Wqf[(k & 511) * 64 + jj];
    }
    g_wpt[(size_t)j * KC + k] = __float2half_rn(w);
}

__global__ void pack_wo_t(const float* __restrict__ Wo) {
    int idx = blockIdx.x * blockDim.x + threadIdx.x;
    int j = idx >> 9, k = idx & 511;
    g_wot[(size_t)j * Dd + k] = __float2half_rn(Wo[(size_t)k * Dd + j]);
}

// ---------------- mma.sync GEMM: 128x128 tiles, K=32, 4-stage cp.async ----------------
// stage: 2 matrices (A, B), each 128 rows x 40 fp16 (32 used + 8 pad)
#define ROWP 40
#define MATB (128 * ROWP * 2)          // 10240 B
#define STAGE_B (2 * MATB)             // 20480 B
#define GSMEM (4 * STAGE_B)            // 81920 B

template<int KDIM, bool CONV>
__global__ __launch_bounds__(256, 2) void mma_gemm(float* __restrict__ Cout,
                                                   const float* __restrict__ bias,
                                                   const float* __restrict__ bqf) {
    extern __shared__ char smc[];
    const uint32_t sbase = smem_u32(smc);
    const int tid = threadIdx.x;
    const int bm = blockIdx.y * 128, bn = blockIdx.x * 128;
    const int NCH = KDIM / 32;

    const __half* Ah = CONV ? g_x_h : g_att_h;
    const __half* Bh = CONV ? g_wpt : g_wot;

    auto load_stage = [&](int c) {
        const int k0 = c * 32;
        const uint32_t sb = sbase + (c & 3) * STAGE_B;
        #pragma unroll
        for (int i = 0; i < 4; i++) {
            int t = tid + i * 256;
            int mat = t >> 9, idx = t & 511, row = idx >> 2, q = idx & 3;
            uint32_t dst = sb + mat * MATB + (row * ROWP + q * 8) * 2;
            const __half* src;
            uint32_t sz = 16;
            if (mat == 0) {
                if (CONV) {
                    int m = bm + row;
                    int b = m / Nn, n = m - b * Nn;
                    int sn = n + (k0 >> 9) - 1;
                    int snc = sn < 0 ? 0 : (sn >= Nn ? Nn - 1 : sn);
                    if (sn != snc) sz = 0;
                    src = Ah + (((size_t)(b * Nn + snc)) << 9) + (k0 & 511) + q * 8;
                } else {
                    src = Ah + (size_t)(bm + row) * KDIM + k0 + q * 8;
                }
            } else {
                src = Bh + (size_t)(bn + row) * KDIM + k0 + q * 8;
            }
            cp16(dst, src, sz);
        }
        CP_COMMIT();
    };

    const int lane = tid & 31, wid = tid >> 5;
    const int wm = (wid >> 2) * 64, wn = (wid & 3) * 32;
    float acc[4][4][4];
    #pragma unroll
    for (int a = 0; a < 4; a++)
        #pragma unroll
        for (int b = 0; b < 4; b++)
            #pragma unroll
            for (int d = 0; d < 4; d++) acc[a][b][d] = 0.f;

    load_stage(0); load_stage(1); load_stage(2);

    for (int c = 0; c < NCH; c++) {
        // ensure chunk c landed (in-order group completion)
        if (c + 2 < NCH)      asm volatile("cp.async.wait_group 2;" ::: "memory");
        else if (c + 1 < NCH) asm volatile("cp.async.wait_group 1;" ::: "memory");
        else                  asm volatile("cp.async.wait_group 0;" ::: "memory");
        __syncthreads();   // single barrier per chunk: also guards slot reuse
        if (c + 3 < NCH) load_stage(c + 3);

        const uint32_t sb = sbase + (c & 3) * STAGE_B;
        #pragma unroll
        for (int kk = 0; kk < 2; kk++) {
            const int koff = kk * 16 + ((lane >> 4) << 3);
            const int arow = lane & 15;
            uint32_t a_h[4][4], b_h[4][2];
            #pragma unroll
            for (int mt = 0; mt < 4; mt++) {
                uint32_t ad = sb + ((wm + mt * 16 + arow) * ROWP + koff) * 2;
                LDSM4(a_h[mt], ad);
            }
            const int brow = ((lane >> 4) << 3) + (lane & 7);
            const int bkoff = kk * 16 + (((lane >> 3) & 1) << 3);
            #pragma unroll
            for (int pr = 0; pr < 2; pr++) {
                uint32_t bd = sb + MATB + ((wn + pr * 16 + brow) * ROWP + bkoff) * 2;
                uint32_t r[4];
                LDSM4(r, bd);
                b_h[pr * 2][0] = r[0]; b_h[pr * 2][1] = r[1];
                b_h[pr * 2 + 1][0] = r[2]; b_h[pr * 2 + 1][1] = r[3];
            }
            #pragma unroll
            for (int mt = 0; mt < 4; mt++)
                #pragma unroll
                for (int nt = 0; nt < 4; nt++)
                    mma16816(acc[mt][nt], a_h[mt], b_h[nt]);
        }
    }

    // ---------------- epilogue ----------------
    const int g = lane >> 2, tg = lane & 3;
    #pragma unroll
    for (int mt = 0; mt < 4; mt++) {
        #pragma unroll
        for (int nt = 0; nt < 4; nt++) {
            int j = bn + wn + nt * 8 + tg * 2;
            #pragma unroll
            for (int half = 0; half < 2; half++) {
                int m = bm + wm + mt * 16 + g + half * 8;
                float d0 = acc[mt][nt][half * 2], d1 = acc[mt][nt][half * 2 + 1];
                if (CONV) {
                    if (j < NC) {
                        *(float2*)(g_qkv + (size_t)m * NC + j) = make_float2(d0, d1);
                    } else if (j < NC + 64) {
                        int jj = j - NC;
                        *(float2*)(g_qf + (size_t)m * 64 + jj) =
                            make_float2(tanhf(d0 + bqf[jj]), tanhf(d1 + bqf[jj + 1]));
                    }
                } else {
                    *(float2*)(Cout + (size_t)m * KDIM + j) =
                        make_float2(d0 + bias[j], d1 + bias[j + 1]);
                }
            }
        }
    }
}

// ---------------- fused LN + residual + attention, one block per batch b ----------------
#define QSTRIDE 1537
#define SM_QKV 0
#define SM_QF  (20 * QSTRIDE)                 // 30740
#define SM_SC  (SM_QF + 20 * 64)              // 32020
#define SM_AV  (SM_SC + 8 * 400)              // 35220
#define SM_FLT (SM_AV + 160)                  // 35380
#define ASMEM  (SM_FLT * 4)                   // 141520 B
#define ATHR 1024

__global__ __launch_bounds__(ATHR) void ln_attn(const float* __restrict__ x,
                                               const float* __restrict__ g0, const float* __restrict__ b0,
                                               const float* __restrict__ g1, const float* __restrict__ b1,
                                               const float* __restrict__ g2, const float* __restrict__ b2,
                                               const float* __restrict__ rel,
                                               const float* __restrict__ gsb,
                                               const float* __restrict__ alpha_p,
                                               const float* __restrict__ Wqp,
                                               const float* __restrict__ bqp) {
    extern __shared__ float sm[];
    const int b = blockIdx.x;
    const int tid = threadIdx.x, lane = tid & 31, wid = tid >> 5;
    const size_t row0 = (size_t)b * Nn;

    for (int i = tid; i < 20 * 1536; i += ATHR) {
        int n = i / 1536, j = i - n * 1536;
        sm[SM_QKV + n * QSTRIDE + j] = g_qkv[(row0 + n) * NC + j];
    }
    for (int i = tid; i < 1280; i += ATHR)
        sm[SM_QF + i] = g_qf[row0 * 64 + i];
    __syncthreads();

    // LN + residual, 60 (n, p) segments over 32 warps
    for (int seg = wid; seg < 60; seg += 32) {
        int n = seg / 3, p = seg - n * 3;
        float* base = sm + SM_QKV + n * QSTRIDE + p * 512;
        const float* g  = (p == 0) ? g0 : (p == 1 ? g1 : g2);
        const float* bb = (p == 0) ? b0 : (p == 1 ? b1 : b2);
        float v[16], s = 0.f, s2 = 0.f;
        #pragma unroll
        for (int i = 0; i < 16; i++) {
            v[i] = base[i * 32 + lane];
            s += v[i]; s2 += v[i] * v[i];
        }
        #pragma unroll
        for (int o = 16; o; o >>= 1) {
            s  += __shfl_xor_sync(0xffffffffu, s, o);
            s2 += __shfl_xor_sync(0xffffffffu, s2, o);
        }
        float mean = s * (1.f / 512.f);
        float inv = rsqrtf(s2 * (1.f / 512.f) - mean * mean + 1e-5f);
        const float* xr = x + (row0 + n) * Dd;
        #pragma unroll
        for (int i = 0; i < 16; i++) {
            int c = i * 32 + lane;
            base[c] = xr[c] + (v[i] - mean) * inv * g[c] + bb[c];
        }
    }
    __syncthreads();

    if (tid < 160) {
        int n = tid >> 3, h = tid & 7;
        float a = 0.f;
        #pragma unroll 8
        for (int j = 0; j < 64; j++) a += sm[SM_QF + n * 64 + j] * Wqp[j * 8 + h];
        sm[SM_AV + tid] = a;
    }
    __syncthreads();

    const float alpha = *alpha_p;
    for (int t = tid; t < 3200; t += ATHR) {
        int h = t / 400, r = t - h * 400;
        int nq = r / 20, nk = r - nq * 20;
        const float* q = sm + SM_QKV + nq * QSTRIDE + h * 64;
        const float* k = sm + SM_QKV + nk * QSTRIDE + 512 + h * 64;
        float d = 0.f;
        #pragma unroll 8
        for (int j = 0; j < 64; j++) d += q[j] * k[j];
        sm[SM_SC + t] = d * 0.125f
                      + rel[(nq - nk + 19) * 8 + h]
                      + alpha * gsb[h * 400 + nq * 20 + nk]
                      + (sm[SM_AV + nq * 8 + h] - sm[SM_AV + nk * 8 + h] + bqp[h]);
    }
    __syncthreads();

    if (tid < 160) {
        float* row = sm + SM_SC + tid * 20;
        float mx = -1e30f;
        #pragma unroll
        for (int k = 0; k < 20; k++) mx = fmaxf(mx, row[k]);
        float s = 0.f;
        #pragma unroll
        for (int k = 0; k < 20; k++) { float e = expf(row[k] - mx); row[k] = e; s += e; }
        float inv = 1.f / s;
        #pragma unroll
        for (int k = 0; k < 20; k++) row[k] *= inv;
    }
    __syncthreads();

    for (int i = tid; i < 10240; i += ATHR) {
        int n = i >> 9, c = i & 511;
        int h = c >> 6, d = c & 63;
        const float* a = sm + SM_SC + (h * 20 + n) * 20;
        float o = 0.f;
        #pragma unroll
        for (int nk = 0; nk < 20; nk++)
            o += a[nk] * sm[SM_QKV + nk * QSTRIDE + 1024 + h * 64 + d];
        g_att_h[(row0 + n) * Dd + c] = __float2half_rn(o);
    }
}

extern "C" void kernel_launch(void* const* d_in, const int* in_sizes, int n_in,
                              void* d_out, int out_size) {
    const float* x   = (const float*)d_in[0];
    const float* Wq  = (const float*)d_in[1];
    const float* Wk  = (const float*)d_in[2];
    const float* Wv  = (const float*)d_in[3];
    const float* gqg = (const float*)d_in[4];
    const float* gqb = (const float*)d_in[5];
    const float* gkg = (const float*)d_in[6];
    const float* gkb = (const float*)d_in[7];
    const float* gvg = (const float*)d_in[8];
    const float* gvb = (const float*)d_in[9];
    const float* rel = (const float*)d_in[10];
    const float* gsb = (const float*)d_in[11];
    const float* alp = (const float*)d_in[12];
    const float* Wqf = (const float*)d_in[13];
    const float* bqf = (const float*)d_in[14];
    const float* Wqp = (const float*)d_in[15];
    const float* bqp = (const float*)d_in[16];
    const float* Wo  = (const float*)d_in[17];
    const float* bo  = (const float*)d_in[18];
    float* out = (float*)d_out;

    static int inited = 0;
    if (!inited) {
        cudaFuncSetAttribute(mma_gemm<KC, true>,  cudaFuncAttributeMaxDynamicSharedMemorySize, GSMEM);
        cudaFuncSetAttribute(mma_gemm<Dd, false>, cudaFuncAttributeMaxDynamicSharedMemorySize, GSMEM);
        cudaFuncSetAttribute(ln_attn, cudaFuncAttributeMaxDynamicSharedMemorySize, ASMEM);
        inited = 1;
    }

    x2h<<<(M_TOT * Dd) / 1024, 256>>>(x);
    pack_w_t<<<(NCP * KC + 255) / 256, 256>>>(Wq, Wk, Wv, Wqf);
    pack_wo_t<<<(Dd * Dd) / 256, 256>>>(Wo);

    dim3 g1(NCP / 128, M_TOT / 128);   // 13 x 320
    mma_gemm<KC, true><<<g1, 256, GSMEM>>>(nullptr, nullptr, bqf);

    ln_attn<<<Bsz, ATHR, ASMEM>>>(x, gqg, gqb, gkg, gkb, gvg, gvb,
                                  rel, gsb, alp, Wqp, bqp);

    dim3 g3(Dd / 128, M_TOT / 128);    // 4 x 320
    mma_gemm<Dd, false><<<g3, 256, GSMEM>>>(out, bo, nullptr);
}